// round 2
// baseline (speedup 1.0000x reference)
#include <cuda_runtime.h>
#include <cstdint>

// EPG simulation: one warp per batch element, one lane per EPG state.
// Output: (n_pulses, batch, 21, 5) fp32 = 440 MB -> HBM-write-bound kernel.

constexpr int N_STATES       = 21;
constexpr int ROW            = N_STATES * 5;   // 105 floats per (pulse, batch)
constexpr int WARPS_PER_BLK  = 8;
constexpr int THREADS        = WARPS_PER_BLK * 32;
constexpr int NP_MAX         = 128;            // max pulses we precompute for

__global__ __launch_bounds__(THREADS)
void epg_kernel(const float* __restrict__ fa,
                const float* __restrict__ ph,
                const float* __restrict__ T1,
                const float* __restrict__ T2,
                const float* __restrict__ B0,
                const float* __restrict__ B1,
                const int*   __restrict__ trp,
                float* __restrict__ out,
                int n_pulses, int n_batch)
{
    __shared__ float sfa[NP_MAX], sc1[NP_MAX], ss1[NP_MAX], sc2[NP_MAX], ss2[NP_MAX];
    __shared__ float stage[WARPS_PER_BLK][ROW];

    const int tid = threadIdx.x;

    // Per-pulse precompute (accurate sincos; done once per block)
    if (tid < n_pulses) {
        float p = ph[tid];
        float s, c;
        sincosf(p, &s, &c);
        sfa[tid] = fa[tid];
        sc1[tid] = c;
        ss1[tid] = s;
        sc2[tid] = c * c - s * s;   // cos(2p)
        ss2[tid] = 2.f * c * s;     // sin(2p)
    }
    __syncthreads();

    const int warp = tid >> 5;
    const int lane = tid & 31;
    const int b = blockIdx.x * WARPS_PER_BLK + warp;
    if (b >= n_batch) return;

    // Robust TR read: accept int32 or float32 bit pattern
    int ti = *trp;
    float TR = (ti > 0 && ti < 1000000) ? (float)ti : __int_as_float(ti);

    const float t1 = T1[b], t2 = T2[b], b0 = B0[b], b1v = B1[b];
    const float E1 = __expf(-TR / t1);
    const float E2 = __expf(-TR / t2);
    const float omE1 = 1.f - E1;
    float b0r, b0i;
    {
        float phi = 6.283185307179586f * b0 * TR * 0.001f;
        sincosf(phi, &b0i, &b0r);
    }

    // State registers for this lane's EPG order
    float fpr = 0.f, fpi = 0.f, fmr = 0.f, fmi = 0.f;
    float Z = (lane == 0) ? 1.f : 0.f;

    float* sw = stage[warp];
    const size_t pstride = (size_t)n_batch * ROW;
    size_t ob = (size_t)b * ROW;   // offset for pulse 0

    for (int p = 0; p < n_pulses; ++p) {
        const float alpha_h = sfa[p] * b1v * 0.5f;
        float sa, ca;
        __sincosf(alpha_h, &sa, &ca);
        const float ca2 = ca * ca, sa2 = sa * sa, casa = ca * sa;
        const float cp = sc1[p], sp = ss1[p];
        const float c2 = sc2[p], s2 = ss2[p];

        // --- RF pulse mixing ---
        // Fp' = ca2*Fp + sa2*conj(Fm)*e^{2ip} + i*casa*Z*e^{ip}
        float nfpr = ca2 * fpr + sa2 * (fmr * c2 + fmi * s2) - casa * Z * sp;
        float nfpi = ca2 * fpi + sa2 * (fmr * s2 - fmi * c2) + casa * Z * cp;
        // Fm' = sa2*conj(Fp)*e^{-2ip} + ca2*Fm - i*casa*Z*e^{-ip}
        float nfmr = sa2 * (fpr * c2 - fpi * s2) + ca2 * fmr - casa * Z * sp;
        float nfmi = -sa2 * (fpr * s2 + fpi * c2) + ca2 * fmi - casa * Z * cp;
        // Z' = casa*Im(Fp e^{-ip} - Fm e^{ip}) + (ca2-sa2)*Z
        float nZ = casa * ((fpi * cp - fpr * sp) - (fmr * sp + fmi * cp))
                 + (ca2 - sa2) * Z;

        // --- relaxation (+ recovery on k=0) ---
        nfpr *= E2; nfpi *= E2; nfmr *= E2; nfmi *= E2;
        nZ = nZ * E1 + ((lane == 0) ? omE1 : 0.f);

        // --- B0 precession (F states only) ---
        float t = nfpr * b0r - nfpi * b0i;
        nfpi = nfpr * b0i + nfpi * b0r;
        nfpr = t;
        t = nfmr * b0r + nfmi * b0i;
        nfmi = nfmi * b0r - nfmr * b0i;
        nfmr = t;

        // --- EPG shift via warp shuffles ---
        fpr = __shfl_up_sync(0xffffffffu, nfpr, 1);
        fpi = __shfl_up_sync(0xffffffffu, nfpi, 1);
        Z   = __shfl_up_sync(0xffffffffu, nZ, 1);
        if (lane == 0) { fpr = 0.f; fpi = 0.f; Z = 0.f; }
        fmr = __shfl_down_sync(0xffffffffu, nfmr, 1);
        fmi = __shfl_down_sync(0xffffffffu, nfmi, 1);
        if (lane >= N_STATES - 1) { fmr = 0.f; fmi = 0.f; }

        // --- stage row in shared (stride 5 coprime 32 -> conflict-free) ---
        if (lane < N_STATES) {
            float* q = sw + lane * 5;
            q[0] = fpr; q[1] = fpi; q[2] = fmr; q[3] = fmi; q[4] = Z;
        }
        __syncwarp();
        // --- coalesced write of 105 contiguous floats ---
        float* o = out + ob;
        #pragma unroll
        for (int i = lane; i < ROW; i += 32) o[i] = sw[i];
        __syncwarp();

        ob += pstride;
    }
}

extern "C" void kernel_launch(void* const* d_in, const int* in_sizes, int n_in,
                              void* d_out, int out_size)
{
    const float* fa = (const float*)d_in[0];
    const float* ph = (const float*)d_in[1];
    const float* T1 = (const float*)d_in[2];
    const float* T2 = (const float*)d_in[3];
    const float* B0 = (const float*)d_in[4];
    const float* B1 = (const float*)d_in[5];
    const int*   tr = (const int*)d_in[6];

    int n_pulses = in_sizes[0];
    int n_batch  = in_sizes[2];
    if (n_pulses > NP_MAX) n_pulses = NP_MAX;

    int blocks = (n_batch + WARPS_PER_BLK - 1) / WARPS_PER_BLK;
    epg_kernel<<<blocks, THREADS>>>(fa, ph, T1, T2, B0, B1, tr,
                                    (float*)d_out, n_pulses, n_batch);
}

// round 4
// speedup vs baseline: 1.0517x; 1.0517x over previous
#include <cuda_runtime.h>
#include <cstdint>

// EPG simulation: one warp per batch element, one lane per EPG state.
// Output (n_pulses, batch, 21, 5) fp32 = 440 MB. Issue/L1-bound -> minimize
// per-pulse instruction count; block-staged float4 coalesced writes.

constexpr int N_STATES = 21;
constexpr int ROW      = N_STATES * 5;       // 105 floats per (pulse, batch)
constexpr int WPB      = 8;                  // warps (batches) per block
constexpr int THREADS  = WPB * 32;
constexpr int NP_MAX   = 128;
constexpr int STAGE    = WPB * ROW;          // 840 floats, 3360 B (16B multiple)
constexpr int COPY4    = STAGE / 4;          // 210 float4 per block-pulse

__global__ __launch_bounds__(THREADS)
void epg_kernel(const float* __restrict__ fa,
                const float* __restrict__ ph,
                const float* __restrict__ T1,
                const float* __restrict__ T2,
                const float* __restrict__ B0,
                const float* __restrict__ B1,
                const int*   __restrict__ trp,
                float* __restrict__ out,
                int n_pulses, int n_batch)
{
    __shared__ float4 spc[NP_MAX];                 // {fa, cos p, sin p, cos 2p}
    __shared__ float  ss2[NP_MAX];                 // sin 2p
    __shared__ __align__(16) float stage[2][STAGE];

    const int tid = threadIdx.x;

    // Per-pulse precompute (accurate sincos, once per block)
    if (tid < n_pulses) {
        float s, c;
        sincosf(ph[tid], &s, &c);
        spc[tid] = make_float4(fa[tid], c, s, c * c - s * s);
        ss2[tid] = 2.f * c * s;
    }
    __syncthreads();

    const int warp = tid >> 5;
    const int lane = tid & 31;
    int b = blockIdx.x * WPB + warp;
    if (b >= n_batch) b = n_batch - 1;             // 16384 % 8 == 0: never taken

    // TR: robust against int32 or float32 bit pattern
    int ti = *trp;
    const float TR = (ti > 0 && ti < 1000000) ? (float)ti : __int_as_float(ti);

    const float E1  = __expf(-TR / T1[b]);
    const float E2  = __expf(-TR / T2[b]);
    const float b1h = B1[b] * 0.5f;
    float b0r, b0i;
    sincosf(6.283185307179586e-3f * B0[b] * TR, &b0i, &b0r);
    const float er  = E2 * b0r, ei = E2 * b0i;     // E2 folded into B0 phasor
    const float rec = (lane == 0) ? (1.f - E1) : 0.f;

    // Per-lane EPG state
    float fpr = 0.f, fpi = 0.f, fmr = 0.f, fmi = 0.f;
    float Z = (lane == 0) ? 1.f : 0.f;

    // Hoisted addresses / predicates
    float* const swp = &stage[0][warp * ROW + lane * 5];   // stride-5: bank-conflict-free
    const bool   st_ok   = (lane < N_STATES);
    const bool   do_copy = (tid < COPY4);
    const size_t pstride4 = (size_t)n_batch * ROW / 4;     // float4 stride per pulse
    float4* ob = (float4*)out + (size_t)blockIdx.x * COPY4 + tid;

    for (int p = 0; p < n_pulses; ++p) {
        const float4 pc = spc[p];
        const float  s2 = ss2[p];
        const float  cp = pc.y, sp = pc.z, c2 = pc.w;

        float sa, ca;
        __sincosf(pc.x * b1h, &sa, &ca);           // alpha/2; |arg| < pi
        const float ca2 = ca * ca, sa2 = sa * sa, casa = ca * sa;
        const float c2a = ca2 - sa2;

        // --- RF mixing ---
        const float t1 = fmr * c2 + fmi * s2;      // conj(Fm)*e^{2ip}
        const float t2 = fmr * s2 - fmi * c2;
        const float t3 = fpr * c2 - fpi * s2;      // conj(Fp)*e^{-2ip}
        const float t4 = fpr * s2 + fpi * c2;
        const float uZ = casa * Z;
        const float ua = uZ * sp, ub = uZ * cp;
        float nfpr = ca2 * fpr + sa2 * t1 - ua;
        float nfpi = ca2 * fpi + sa2 * t2 + ub;
        float nfmr = sa2 * t3 + ca2 * fmr - ua;
        float nfmi = ca2 * fmi - sa2 * t4 - ub;
        const float w = (fpi * cp - fpr * sp) - (fmr * sp + fmi * cp);
        const float nZ = (casa * w + c2a * Z) * E1 + rec;   // relax + recovery

        // --- relaxation + B0 precession (merged phasor) ---
        const float xr = nfpr * er - nfpi * ei;
        const float xi = nfpr * ei + nfpi * er;
        const float yr = nfmr * er + nfmi * ei;    // conj phasor for Fm
        const float yi = nfmi * er - nfmr * ei;

        // --- EPG shift via shuffles ---
        fpr = __shfl_up_sync(0xffffffffu, xr, 1);
        fpi = __shfl_up_sync(0xffffffffu, xi, 1);
        Z   = __shfl_up_sync(0xffffffffu, nZ, 1);
        if (lane == 0) { fpr = 0.f; fpi = 0.f; Z = 0.f; }
        fmr = __shfl_down_sync(0xffffffffu, yr, 1);
        fmi = __shfl_down_sync(0xffffffffu, yi, 1);
        if (lane >= N_STATES - 1) { fmr = 0.f; fmi = 0.f; }

        // --- stage this warp's 105-float row (double buffer) ---
        float* sw = swp + (p & 1) * STAGE;
        if (st_ok) { sw[0] = fpr; sw[1] = fpi; sw[2] = fmr; sw[3] = fmi; sw[4] = Z; }
        __syncthreads();
        // --- block-coalesced float4 copy-out (210 of 256 threads) ---
        if (do_copy) *ob = ((const float4*)stage[p & 1])[tid];
        ob += pstride4;
        // no trailing barrier: buffer (p&1) is next written at pulse p+2,
        // which is ordered after sync(p+1), which is after this copy.
    }
}

extern "C" void kernel_launch(void* const* d_in, const int* in_sizes, int n_in,
                              void* d_out, int out_size)
{
    const float* fa = (const float*)d_in[0];
    const float* ph = (const float*)d_in[1];
    const float* T1 = (const float*)d_in[2];
    const float* T2 = (const float*)d_in[3];
    const float* B0 = (const float*)d_in[4];
    const float* B1 = (const float*)d_in[5];
    const int*   tr = (const int*)d_in[6];

    int n_pulses = in_sizes[0];
    int n_batch  = in_sizes[2];
    if (n_pulses > NP_MAX) n_pulses = NP_MAX;

    int blocks = (n_batch + WPB - 1) / WPB;
    epg_kernel<<<blocks, THREADS>>>(fa, ph, T1, T2, B0, B1, tr,
                                    (float*)d_out, n_pulses, n_batch);
}

// round 5
// speedup vs baseline: 1.1961x; 1.1373x over previous
#include <cuda_runtime.h>
#include <cstdint>

// EPG simulation, issue-bound. One warp per batch element, one lane per state.
// All per-(batch,pulse) transition coefficients precomputed into shared once;
// inner loop is pure FFMA + shuffle-shift + block-coalesced float4 copy-out.

constexpr int N_STATES = 21;
constexpr int ROW      = N_STATES * 5;   // 105 floats per (pulse,batch)
constexpr int WPB      = 8;              // warps (batches) per block
constexpr int THREADS  = WPB * 32;
constexpr int NP       = 64;             // fixed problem size
constexpr int STAGE    = WPB * ROW;      // 840 floats
constexpr int COPY4    = STAGE / 4;      // 210 float4 per block-pulse
constexpr int CSTRIDE  = 12;             // coef floats per (warp,pulse), 16B-aligned

__global__ __launch_bounds__(THREADS)
void epg_kernel(const float* __restrict__ fa,
                const float* __restrict__ ph,
                const float* __restrict__ T1,
                const float* __restrict__ T2,
                const float* __restrict__ B0,
                const float* __restrict__ B1,
                const int*   __restrict__ trp,
                float* __restrict__ out,
                int n_pulses, int n_batch)
{
    __shared__ __align__(16) float coef[WPB][NP][CSTRIDE];   // 24576 B
    __shared__ __align__(16) float stage[2][STAGE];          // 6720 B

    const int tid = threadIdx.x;

    // TR: robust against int32 or float32 bit pattern
    const int tri = *trp;
    const float TR = (tri > 0 && tri < 1000000) ? (float)tri : __int_as_float(tri);

    // ---- one-time coefficient precompute: (warp w, pulse p) pairs ----
    const int npair = WPB * n_pulses;
    for (int i = tid; i < npair; i += THREADS) {
        const int w = i / n_pulses;
        const int p = i - w * n_pulses;
        int b = blockIdx.x * WPB + w;
        if (b >= n_batch) b = n_batch - 1;

        const float E1 = __expf(-TR / T1[b]);
        const float E2 = __expf(-TR / T2[b]);
        float b0r, b0i;
        sincosf(6.283185307179586e-3f * B0[b] * TR, &b0i, &b0r);
        const float er = E2 * b0r, ei = E2 * b0i;      // E2 * e^{i theta}

        float sp, cp;
        sincosf(ph[p], &sp, &cp);                      // e^{i phi}
        const float c2 = cp * cp - sp * sp;            // cos 2phi
        const float s2 = 2.f * cp * sp;                // sin 2phi

        float sa, ca;
        __sincosf(fa[p] * B1[b] * 0.5f, &sa, &ca);     // alpha/2, |arg|<pi
        const float ca2 = ca * ca, sa2 = sa * sa, casa = ca * sa;
        const float c2a = ca2 - sa2;

        const float w2r = er * c2 - ei * s2;           // E2 e^{i(theta+2phi)}
        const float w2i = er * s2 + ei * c2;
        const float w1r = er * cp - ei * sp;           // E2 e^{i(theta+phi)}
        const float w1i = er * sp + ei * cp;
        const float q1  = casa * E1;

        float4* dst = (float4*)&coef[w][p][0];
        dst[0] = make_float4(ca2 * er, ca2 * ei,       // A
                             sa2 * w2r, sa2 * w2i);    // B
        dst[1] = make_float4(-casa * w1i, casa * w1r,  // C = i*casa*w1
                             q1 * cp, q1 * sp);        // zc, zs
        coef[w][p][8] = c2a * E1;                      // q2
    }
    __syncthreads();

    // ---- main scan ----
    const int warp = tid >> 5;
    const int lane = tid & 31;
    int b = blockIdx.x * WPB + warp;
    if (b >= n_batch) b = n_batch - 1;                 // 16384 % 8 == 0: never taken

    const float E1  = __expf(-TR / T1[b]);
    const float rec = (lane == 0) ? (1.f - E1) : 0.f;

    float fpr = 0.f, fpi = 0.f, fmr = 0.f, fmi = 0.f;
    float Z = (lane == 0) ? 1.f : 0.f;

    const float* cf = &coef[warp][0][0];
    float* const swp = &stage[0][warp * ROW + lane * 5];   // stride 5: conflict-free
    const bool  st_ok   = (lane < N_STATES);
    const bool  do_copy = (tid < COPY4);
    const size_t pstride4 = (size_t)n_batch * ROW / 4;
    float4* ob = (float4*)out + (size_t)blockIdx.x * COPY4 + tid;

    for (int p = 0; p < n_pulses; ++p) {
        const float4 A  = *(const float4*)cf;          // Ar Ai Br Bi
        const float4 C  = *(const float4*)(cf + 4);    // Cr Ci zc zs
        const float  q2 = cf[8];
        cf += CSTRIDE;

        // Fp' = A*Fp + B*conj(Fm) + C*Z ;  Fm' mirrors with same coefficients
        const float nfpr = A.x*fpr - A.y*fpi + A.z*fmr + A.w*fmi + C.x*Z;
        const float nfpi = A.x*fpi + A.y*fpr - A.z*fmi + A.w*fmr + C.y*Z;
        const float nfmr = A.x*fmr + A.y*fmi + A.z*fpr - A.w*fpi + C.x*Z;
        const float nfmi = A.x*fmi - A.y*fmr - A.z*fpi - A.w*fpr - C.y*Z;
        const float Sr = fpr + fmr;
        const float Si = fpi - fmi;
        const float nZ = q2*Z + C.z*Si - C.w*Sr + rec;

        // EPG shift via shuffles
        fpr = __shfl_up_sync(0xffffffffu, nfpr, 1);
        fpi = __shfl_up_sync(0xffffffffu, nfpi, 1);
        Z   = __shfl_up_sync(0xffffffffu, nZ, 1);
        if (lane == 0) { fpr = 0.f; fpi = 0.f; Z = 0.f; }
        fmr = __shfl_down_sync(0xffffffffu, nfmr, 1);
        fmi = __shfl_down_sync(0xffffffffu, nfmi, 1);
        if (lane >= N_STATES - 1) { fmr = 0.f; fmi = 0.f; }

        // stage this warp's 105-float row (double buffer)
        float* sw = swp + (p & 1) * STAGE;
        if (st_ok) { sw[0] = fpr; sw[1] = fpi; sw[2] = fmr; sw[3] = fmi; sw[4] = Z; }
        __syncthreads();
        // block-coalesced float4 copy-out (210 of 256 threads)
        if (do_copy) *ob = ((const float4*)stage[p & 1])[tid];
        ob += pstride4;
        // buffer (p&1) next written at pulse p+2, ordered by sync(p+1).
    }
}

extern "C" void kernel_launch(void* const* d_in, const int* in_sizes, int n_in,
                              void* d_out, int out_size)
{
    const float* fa = (const float*)d_in[0];
    const float* ph = (const float*)d_in[1];
    const float* T1 = (const float*)d_in[2];
    const float* T2 = (const float*)d_in[3];
    const float* B0 = (const float*)d_in[4];
    const float* B1 = (const float*)d_in[5];
    const int*   tr = (const int*)d_in[6];

    int n_pulses = in_sizes[0];
    int n_batch  = in_sizes[2];
    if (n_pulses > NP) n_pulses = NP;

    int blocks = (n_batch + WPB - 1) / WPB;
    epg_kernel<<<blocks, THREADS>>>(fa, ph, T1, T2, B0, B1, tr,
                                    (float*)d_out, n_pulses, n_batch);
}

// round 7
// speedup vs baseline: 1.2200x; 1.0200x over previous
#include <cuda_runtime.h>
#include <cstdint>

// EPG simulation. One warp per batch element; lane L holds state k=(L+t)&31
// (role rotation: Fp/Z shift is identity, Fm shift = fixed lane rotation by 2).
// Coefficients precomputed per (batch,pulse) into shared; inner loop is pure
// FFMA + 2 shuffles + staged block-coalesced float4 copy-out.

constexpr int N_STATES = 21;
constexpr int ROW      = N_STATES * 5;   // 105 floats per (pulse,batch)
constexpr int WPB      = 4;              // warps (batches) per block
constexpr int THREADS  = WPB * 32;
constexpr int NP       = 64;             // fixed problem size
constexpr int STAGE    = WPB * ROW;      // 420 floats = 105 float4 exactly
constexpr int COPY4    = STAGE / 4;      // 105
constexpr int CSTRIDE  = 12;             // coef floats per (warp,pulse)

__global__ __launch_bounds__(THREADS)
void epg_kernel(const float* __restrict__ fa,
                const float* __restrict__ ph,
                const float* __restrict__ T1,
                const float* __restrict__ T2,
                const float* __restrict__ B0,
                const float* __restrict__ B1,
                const int*   __restrict__ trp,
                float* __restrict__ out,
                int n_pulses, int n_batch)
{
    __shared__ __align__(16) float coef[WPB][NP][CSTRIDE];   // 12288 B
    __shared__ __align__(16) float stage[2][STAGE];          // 3360 B

    const int tid = threadIdx.x;

    // TR: robust against int32 or float32 bit pattern
    const int tri = *trp;
    const float TR = (tri > 0 && tri < 1000000) ? (float)tri : __int_as_float(tri);

    // ---- one-time coefficient precompute: (warp w, pulse p) pairs ----
    const int npair = WPB * n_pulses;
    for (int i = tid; i < npair; i += THREADS) {
        const int w = i / n_pulses;
        const int p = i - w * n_pulses;
        int b = blockIdx.x * WPB + w;
        if (b >= n_batch) b = n_batch - 1;

        const float E1 = __expf(-TR / T1[b]);
        const float E2 = __expf(-TR / T2[b]);
        float b0r, b0i;
        sincosf(6.283185307179586e-3f * B0[b] * TR, &b0i, &b0r);
        const float er = E2 * b0r, ei = E2 * b0i;      // E2 * e^{i theta}

        float sp, cp;
        sincosf(ph[p], &sp, &cp);
        const float c2 = cp * cp - sp * sp;            // cos 2phi
        const float s2 = 2.f * cp * sp;                // sin 2phi

        float sa, ca;
        __sincosf(fa[p] * B1[b] * 0.5f, &sa, &ca);     // alpha/2, |arg|<pi
        const float ca2 = ca * ca, sa2 = sa * sa, casa = ca * sa;

        const float w2r = er * c2 - ei * s2;           // E2 e^{i(theta+2phi)}
        const float w2i = er * s2 + ei * c2;
        const float w1r = er * cp - ei * sp;           // E2 e^{i(theta+phi)}
        const float w1i = er * sp + ei * cp;
        const float q1  = casa * E1;

        float4* dst = (float4*)&coef[w][p][0];
        dst[0] = make_float4(ca2 * er, ca2 * ei,       // A
                             sa2 * w2r, sa2 * w2i);    // B
        dst[1] = make_float4(-casa * w1i, casa * w1r,  // C = i*casa*w1
                             q1 * cp, q1 * sp);        // zc, zs
        coef[w][p][8] = (ca2 - sa2) * E1;              // q2
    }
    __syncthreads();

    // ---- main scan ----
    const int warp = tid >> 5;
    const int lane = tid & 31;
    int b = blockIdx.x * WPB + warp;
    if (b >= n_batch) b = n_batch - 1;                 // 16384 % 4 == 0: never taken

    const float omE1 = 1.f - __expf(-TR / T1[b]);

    int k = lane;                                      // state held at t=0
    const int src2 = (lane + 2) & 31;                  // Fm rotation source
    float fpr = 0.f, fpi = 0.f, fmr = 0.f, fmi = 0.f;
    float Z = (lane == 0) ? 1.f : 0.f;

    const float* cf = &coef[warp][0][0];
    const size_t pstride4 = (size_t)n_batch * ROW / 4;
    float4* ob = (float4*)out + (size_t)blockIdx.x * COPY4 + tid;

    for (int p = 0; p < n_pulses; ++p) {
        const float4 A  = *(const float4*)cf;          // Ar Ai Br Bi
        const float4 C  = *(const float4*)(cf + 4);    // Cr Ci zc zs
        const float  q2 = cf[8];
        cf += CSTRIDE;

        // RF + relax + precession, all folded into A,B,C,q2,zc,zs
        const float nfpr = A.x*fpr - A.y*fpi + A.z*fmr + A.w*fmi + C.x*Z;
        const float nfpi = A.x*fpi + A.y*fpr - A.z*fmi + A.w*fmr + C.y*Z;
        const float nfmr = A.x*fmr + A.y*fmi + A.z*fpr - A.w*fpi + C.x*Z;
        const float nfmi = A.x*fmi - A.y*fmr - A.z*fpi - A.w*fpr - C.y*Z;
        const float Sr = fpr + fmr;
        const float Si = fpi - fmi;
        float nZ = q2*Z + C.z*Si - C.w*Sr;
        nZ += (k == 0) ? omE1 : 0.f;                   // recovery at state 0 (pre-shift)

        // EPG shift in rotated frame: Fp/Z identity, Fm from lane+2 (wraps)
        const float smr = __shfl_sync(0xffffffffu, nfmr, src2);
        const float smi = __shfl_sync(0xffffffffu, nfmi, src2);
        const bool zp = (k == 31);                     // new k==0: zero Fp,Z
        const bool zf = (k == 19);                     // new k==20: zero Fm
        k = (k + 1) & 31;
        fpr = zp ? 0.f : nfpr;
        fpi = zp ? 0.f : nfpi;
        Z   = zp ? 0.f : nZ;
        fmr = zf ? 0.f : smr;
        fmi = zf ? 0.f : smi;

        // stage this warp's row (double buffer); k*5 mod 32 distinct -> conflict-free
        if (k < N_STATES) {
            float* sw = &stage[p & 1][warp * ROW + k * 5];
            sw[0] = fpr; sw[1] = fpi; sw[2] = fmr; sw[3] = fmi; sw[4] = Z;
        }
        __syncthreads();
        // block-coalesced float4 copy-out (105 of 128 threads)
        if (tid < COPY4) *ob = ((const float4*)stage[p & 1])[tid];
        ob += pstride4;
        // buffer (p&1) next written at pulse p+2, ordered by sync(p+1).
    }
}

extern "C" void kernel_launch(void* const* d_in, const int* in_sizes, int n_in,
                              void* d_out, int out_size)
{
    const float* fa = (const float*)d_in[0];
    const float* ph = (const float*)d_in[1];
    const float* T1 = (const float*)d_in[2];
    const float* T2 = (const float*)d_in[3];
    const float* B0 = (const float*)d_in[4];
    const float* B1 = (const float*)d_in[5];
    const int*   tr = (const int*)d_in[6];

    int n_pulses = in_sizes[0];
    int n_batch  = in_sizes[2];
    if (n_pulses > NP) n_pulses = NP;

    int blocks = (n_batch + WPB - 1) / WPB;
    epg_kernel<<<blocks, THREADS>>>(fa, ph, T1, T2, B0, B1, tr,
                                    (float*)d_out, n_pulses, n_batch);
}

// round 9
// speedup vs baseline: 1.5250x; 1.2500x over previous
#include <cuda_runtime.h>
#include <cstdint>

// EPG simulation, thread-per-batch: all 21 states (105 floats) live in
// registers via a fully-unrolled in-place sweep; EPG shift is realized by
// carry variables (up-shift) and offset writes (down-shift) -> no shuffles,
// no cross-warp traffic. One warp = 32 batches. Output staged per-warp in
// shared and written as coalesced float4.

constexpr int NS   = 21;
constexpr int ROW  = NS * 5;          // 105 floats per (pulse,batch)
constexpr int NP   = 64;              // fixed pulse count
constexpr int TPB  = 32;              // one warp per block
constexpr int ST_F = TPB * ROW;       // 3360 floats staged per warp-pulse
constexpr int ST4  = ST_F / 4;        // 840 float4

__global__ __launch_bounds__(TPB)
void epg_kernel(const float* __restrict__ fa,
                const float* __restrict__ ph,
                const float* __restrict__ T1,
                const float* __restrict__ T2,
                const float* __restrict__ B0,
                const float* __restrict__ B1,
                const int*   __restrict__ trp,
                float* __restrict__ out,
                int n_pulses, int n_batch)
{
    __shared__ __align__(16) float4 pc4[NP];     // {fa, cos p, sin p, cos 2p}
    __shared__ float                ps2[NP];     // sin 2p
    __shared__ __align__(16) float  stage[ST_F]; // packed 32 rows x 105

    const int lane = threadIdx.x;

    // Pulse constants (once per block)
    for (int p = lane; p < n_pulses; p += TPB) {
        float s, c;
        sincosf(ph[p], &s, &c);
        pc4[p] = make_float4(fa[p], c, s, c * c - s * s);
        ps2[p] = 2.f * c * s;
    }
    __syncwarp();

    int b = blockIdx.x * TPB + lane;
    if (b >= n_batch) b = n_batch - 1;           // 16384 % 32 == 0: never taken

    const int tri = *trp;
    const float TR = (tri > 0 && tri < 1000000) ? (float)tri : __int_as_float(tri);

    const float E1  = __expf(-TR / T1[b]);
    const float E2  = __expf(-TR / T2[b]);
    const float rec = 1.f - E1;
    const float b1h = B1[b] * 0.5f;
    float b0r, b0i;
    sincosf(6.283185307179586e-3f * B0[b] * TR, &b0i, &b0r);
    const float er = E2 * b0r, ei = E2 * b0i;    // E2 * e^{i theta}

    // Full state in registers (static indices via full unroll)
    float Fpr[NS], Fpi[NS], Fmr[NS], Fmi[NS], Zz[NS];
    #pragma unroll
    for (int k = 0; k < NS; ++k) { Fpr[k]=0.f; Fpi[k]=0.f; Fmr[k]=0.f; Fmi[k]=0.f; Zz[k]=0.f; }
    Zz[0] = 1.f;

    float* const myrow = stage + lane * ROW;     // stride 105 = 9 mod 32: STS conflict-free
    const size_t pst4  = (size_t)n_batch * ROW / 4;
    float4* out4 = (float4*)out + (size_t)blockIdx.x * ST4;

    for (int p = 0; p < n_pulses; ++p) {
        const float4 pc = pc4[p];
        const float  s2 = ps2[p];
        const float  cp = pc.y, sp = pc.z, c2 = pc.w;

        // Per-thread coefficients for this (batch, pulse)
        float sa, ca;
        __sincosf(pc.x * b1h, &sa, &ca);
        const float ca2 = ca * ca, sa2 = sa * sa, casa = ca * sa;
        const float ar = ca2 * er, ai = ca2 * ei;              // A
        const float w2r = er * c2 - ei * s2, w2i = er * s2 + ei * c2;
        const float br = sa2 * w2r, bi = sa2 * w2i;            // B
        const float w1r = er * cp - ei * sp, w1i = er * sp + ei * cp;
        const float cr = -casa * w1i, ci = casa * w1r;         // C = i*casa*w1
        const float q1 = casa * E1;
        const float zc = q1 * cp, zs = q1 * sp;
        const float q2 = (ca2 - sa2) * E1;

        // In-place ascending sweep: carries realize the Fp/Z up-shift,
        // Fm[k-1] <- mix(old slot k) realizes the Fm down-shift.
        float cFr = 0.f, cFi = 0.f, cZ = 0.f;    // new slot-k values (from k-1); k=0 -> zeros
        #pragma unroll
        for (int k = 0; k < NS; ++k) {
            const float ofr = Fpr[k], ofi = Fpi[k];
            const float omr = Fmr[k], omi = Fmi[k];
            const float oz  = Zz[k];
            if (k > 0) {                          // new Fm for slot k-1 (uses old slot k)
                Fmr[k-1] = ar*omr + ai*omi + br*ofr - bi*ofi + cr*oz;
                Fmi[k-1] = ar*omi - ai*omr - br*ofi - bi*ofr - ci*oz;
            }
            Fpr[k] = cFr; Fpi[k] = cFi; Zz[k] = cZ;
            cFr = ar*ofr - ai*ofi + br*omr + bi*omi + cr*oz;   // -> slot k+1
            cFi = ar*ofi + ai*ofr - br*omi + bi*omr + ci*oz;
            cZ  = q2*oz + zc*(ofi - omi) - zs*(ofr + omr);
            if (k == 0) cZ += rec;                // recovery at old state 0 (static)
        }
        Fmr[NS-1] = 0.f; Fmi[NS-1] = 0.f;         // reference zeroes last Fm state

        // Stage this thread's packed 105-float row (scalar STS, conflict-free)
        #pragma unroll
        for (int k = 0; k < NS; ++k) {
            myrow[k*5+0] = Fpr[k]; myrow[k*5+1] = Fpi[k];
            myrow[k*5+2] = Fmr[k]; myrow[k*5+3] = Fmi[k];
            myrow[k*5+4] = Zz[k];
        }
        __syncwarp();
        // Coalesced copy-out: 840 float4 (26 full rounds + 8 lanes)
        {
            const float4* s4 = (const float4*)stage;
            float4* o4 = out4 + (size_t)p * pst4;
            #pragma unroll
            for (int r = 0; r < 26; ++r) o4[lane + r*32] = s4[lane + r*32];
            if (lane < ST4 - 26*32) o4[lane + 26*32] = s4[lane + 26*32];
        }
        __syncwarp();   // copy reads complete before next pulse's STS overwrite
    }
}

extern "C" void kernel_launch(void* const* d_in, const int* in_sizes, int n_in,
                              void* d_out, int out_size)
{
    const float* fa = (const float*)d_in[0];
    const float* ph = (const float*)d_in[1];
    const float* T1 = (const float*)d_in[2];
    const float* T2 = (const float*)d_in[3];
    const float* B0 = (const float*)d_in[4];
    const float* B1 = (const float*)d_in[5];
    const int*   tr = (const int*)d_in[6];

    int n_pulses = in_sizes[0];
    int n_batch  = in_sizes[2];
    if (n_pulses > NP) n_pulses = NP;

    int blocks = (n_batch + TPB - 1) / TPB;      // 512 one-warp blocks
    epg_kernel<<<blocks, TPB>>>(fa, ph, T1, T2, B0, B1, tr,
                                (float*)d_out, n_pulses, n_batch);
}

// round 10
// speedup vs baseline: 1.5635x; 1.0252x over previous
#include <cuda_runtime.h>
#include <cstdint>

// EPG simulation, 4 threads per batch: each thread owns 6 of 24 state slots
// (21 real + 3 contained junk). The in-place carry sweep splits exactly at
// thread boundaries: carry-out of slot 5 == carry-in of next thread; the
// first-slot Fm-mix == previous thread's Fm[5]. 5 floats shuffled per pulse.
// 2048 warps chip-wide (vs 512 for thread-per-batch) -> 4x latency hiding.

constexpr int NS   = 21;
constexpr int ROW  = NS * 5;            // 105 floats per (pulse,batch)
constexpr int NP   = 64;
constexpr int WARPS = 4;                // warps per block
constexpr int THREADS = WARPS * 32;     // 128 -> 32 batches per block
constexpr int BPW  = 8;                 // batches per warp
constexpr int WST  = BPW * ROW;         // 840 floats per warp stage
constexpr int WST4 = WST / 4;           // 210 float4

__global__ __launch_bounds__(THREADS)
void epg_kernel(const float* __restrict__ fa,
                const float* __restrict__ ph,
                const float* __restrict__ T1,
                const float* __restrict__ T2,
                const float* __restrict__ B0,
                const float* __restrict__ B1,
                const int*   __restrict__ trp,
                float* __restrict__ out,
                int n_pulses, int n_batch)
{
    __shared__ __align__(16) float4 pc4[NP];            // {fa, cos p, sin p, cos 2p}
    __shared__ float                ps2[NP];            // sin 2p
    __shared__ __align__(16) float  stage[WARPS][2][WST];  // 26880 B double-buffered

    const int tid  = threadIdx.x;
    const int warp = tid >> 5;
    const int lane = tid & 31;
    const int bw   = lane >> 2;          // batch within warp (0..7)
    const int t    = lane & 3;           // fragment within batch (0..3)

    // Pulse constants once per block
    for (int p = tid; p < n_pulses; p += THREADS) {
        float s, c;
        sincosf(ph[p], &s, &c);
        pc4[p] = make_float4(fa[p], c, s, c * c - s * s);
        ps2[p] = 2.f * c * s;
    }
    __syncthreads();

    int b = blockIdx.x * (WARPS * BPW) + warp * BPW + bw;
    if (b >= n_batch) b = n_batch - 1;   // 16384 % 32 == 0: never taken

    const int tri = *trp;
    const float TR = (tri > 0 && tri < 1000000) ? (float)tri : __int_as_float(tri);

    const float E1  = __expf(-TR / T1[b]);
    const float E2  = __expf(-TR / T2[b]);
    const float rec = 1.f - E1;
    const float b1h = B1[b] * 0.5f;
    float b0r, b0i;
    sincosf(6.283185307179586e-3f * B0[b] * TR, &b0i, &b0r);
    const float er = E2 * b0r, ei = E2 * b0i;   // E2 * e^{i theta}

    // 6 local slots; global state k = 6*t + j (t=3: 18..20 real, 21..23 junk)
    float Fpr[6], Fpi[6], Fmr[6], Fmi[6], Zz[6];
    #pragma unroll
    for (int j = 0; j < 6; ++j) { Fpr[j]=0.f; Fpi[j]=0.f; Fmr[j]=0.f; Fmi[j]=0.f; Zz[j]=0.f; }
    if (t == 0) Zz[0] = 1.f;             // global state 0

    const bool t0 = (t == 0), t3 = (t == 3);
    const size_t pst4 = (size_t)n_batch * ROW / 4;
    float4* out4 = (float4*)out
                 + ((size_t)blockIdx.x * (WARPS * BPW) + warp * BPW) * ROW / 4;

    for (int p = 0; p < n_pulses; ++p) {
        const float4 pc = pc4[p];
        const float  s2 = ps2[p];
        const float  cp = pc.y, sp = pc.z, c2 = pc.w;

        // Per-thread coefficients (duplicated across the 4 fragments of a batch)
        float sa, ca;
        __sincosf(pc.x * b1h, &sa, &ca);
        const float ca2 = ca*ca, sa2 = sa*sa, casa = ca*sa;
        const float ar = ca2*er, ai = ca2*ei;                         // A
        const float w2r = er*c2 - ei*s2, w2i = er*s2 + ei*c2;
        const float br = sa2*w2r, bi = sa2*w2i;                       // B
        const float w1r = er*cp - ei*sp, w1i = er*sp + ei*cp;
        const float cr = -casa*w1i, ci = casa*w1r;                    // C = i*casa*w1
        const float q1 = casa*E1;
        const float zc = q1*cp, zs = q1*sp;
        const float q2 = (ca2 - sa2)*E1;

        // Boundary values from OLD state:
        //  carry out of local slot 5  -> next thread's slot 0
        const float ocFr = ar*Fpr[5] - ai*Fpi[5] + br*Fmr[5] + bi*Fmi[5] + cr*Zz[5];
        const float ocFi = ar*Fpi[5] + ai*Fpr[5] - br*Fmi[5] + bi*Fmr[5] + ci*Zz[5];
        const float ocZ  = q2*Zz[5] + zc*(Fpi[5]-Fmi[5]) - zs*(Fpr[5]+Fmr[5]);
        //  Fm-mix of local slot 0     -> previous thread's slot 5
        const float oMr  = ar*Fmr[0] + ai*Fmi[0] + br*Fpr[0] - bi*Fpi[0] + cr*Zz[0];
        const float oMi  = ar*Fmi[0] - ai*Fmr[0] - br*Fpi[0] - bi*Fpr[0] - ci*Zz[0];

        float icFr = __shfl_up_sync(0xffffffffu, ocFr, 1);
        float icFi = __shfl_up_sync(0xffffffffu, ocFi, 1);
        float icZ  = __shfl_up_sync(0xffffffffu, ocZ,  1);
        float iMr  = __shfl_down_sync(0xffffffffu, oMr, 1);
        float iMi  = __shfl_down_sync(0xffffffffu, oMi, 1);
        if (t0) { icFr = 0.f; icFi = 0.f; icZ = 0.f; }   // global slot 0 zeroed post-shift
        if (t3) { iMr = 0.f; iMi = 0.f; }                // beyond tracked states

        // Local in-place sweep, carries realize the shift
        float cFr = icFr, cFi = icFi, cZ = icZ;
        #pragma unroll
        for (int j = 0; j < 6; ++j) {
            const float ofr = Fpr[j], ofi = Fpi[j];
            const float omr = Fmr[j], omi = Fmi[j];
            const float oz  = Zz[j];
            if (j > 0) {                 // new Fm for slot j-1 (from old slot j)
                Fmr[j-1] = ar*omr + ai*omi + br*ofr - bi*ofi + cr*oz;
                Fmi[j-1] = ar*omi - ai*omr - br*ofi - bi*ofr - ci*oz;
            }
            Fpr[j] = cFr; Fpi[j] = cFi; Zz[j] = cZ;
            cFr = ar*ofr - ai*ofi + br*omr + bi*omi + cr*oz;
            cFi = ar*ofi + ai*ofr - br*omi + bi*omr + ci*oz;
            cZ  = q2*oz + zc*(ofi - omi) - zs*(ofr + omr);
            if (j == 0 && t0) cZ += rec; // recovery (old state 0 -> lands in state 1)
        }
        Fmr[5] = iMr; Fmi[5] = iMi;      // from next thread's old slot 0
        if (t3) { Fmr[2] = 0.f; Fmi[2] = 0.f; }   // global Fm[20] = 0 (seals junk)

        // Stage: thread stores its real states (t<3: 6, t==3: 3) packed
        const int buf = p & 1;
        {
            float* row = &stage[warp][buf][bw * ROW + t * 30];
            const int jmax = t3 ? 3 : 6;
            #pragma unroll
            for (int j = 0; j < 6; ++j) {
                if (j < jmax) {
                    row[j*5+0] = Fpr[j]; row[j*5+1] = Fpi[j];
                    row[j*5+2] = Fmr[j]; row[j*5+3] = Fmi[j];
                    row[j*5+4] = Zz[j];
                }
            }
        }
        __syncwarp();
        // Coalesced copy-out: 210 float4 per warp (6 rounds + 18-lane tail)
        {
            const float4* s4 = (const float4*)stage[warp][buf];
            float4* o4 = out4 + (size_t)p * pst4;
            #pragma unroll
            for (int r = 0; r < 6; ++r) o4[lane + r*32] = s4[lane + r*32];
            if (lane < WST4 - 6*32) o4[lane + 6*32] = s4[lane + 6*32];
        }
        // no second barrier: buffer buf is next written at pulse p+2, which is
        // after syncwarp(p+1); each lane's copy(p) precedes its syncwarp(p+1).
    }
}

extern "C" void kernel_launch(void* const* d_in, const int* in_sizes, int n_in,
                              void* d_out, int out_size)
{
    const float* fa = (const float*)d_in[0];
    const float* ph = (const float*)d_in[1];
    const float* T1 = (const float*)d_in[2];
    const float* T2 = (const float*)d_in[3];
    const float* B0 = (const float*)d_in[4];
    const float* B1 = (const float*)d_in[5];
    const int*   tr = (const int*)d_in[6];

    int n_pulses = in_sizes[0];
    int n_batch  = in_sizes[2];
    if (n_pulses > NP) n_pulses = NP;

    int batches_per_block = WARPS * BPW;                     // 32
    int blocks = (n_batch + batches_per_block - 1) / batches_per_block;  // 512
    epg_kernel<<<blocks, THREADS>>>(fa, ph, T1, T2, B0, B1, tr,
                                    (float*)d_out, n_pulses, n_batch);
}